// round 6
// baseline (speedup 1.0000x reference)
#include <cuda_runtime.h>
#include <cstdint>
#include <cstddef>

#define NUM_HEADS 8
#define NTOK 50
#define HEADDIM 32
#define NWIN 2048
#define CDIM 256

// Scratch (allocation-free rule: __device__ globals)
__device__ float g_qkv[3ULL * NWIN * NUM_HEADS * NTOK * HEADDIM];  // [which][b][h][t][d]
__device__ float g_att[(size_t)NWIN * NTOK * CDIM];                // [b][t][h*32+d]
__device__ float g_bias[NUM_HEADS * NTOK * NTOK];                  // padded bias [h][i][j]

__device__ __forceinline__ uint32_t f2tf32(float f) {
    uint32_t r;
    asm("cvt.rna.tf32.f32 %0, %1;" : "=r"(r) : "f"(f));
    return r;
}

__device__ __forceinline__ void mma_tf32(float d[4],
                                         uint32_t a0, uint32_t a1, uint32_t a2, uint32_t a3,
                                         uint32_t b0, uint32_t b1) {
    asm volatile(
        "mma.sync.aligned.m16n8k8.row.col.f32.tf32.tf32.f32 "
        "{%0,%1,%2,%3}, {%4,%5,%6,%7}, {%8,%9}, {%0,%1,%2,%3};\n"
        : "+f"(d[0]), "+f"(d[1]), "+f"(d[2]), "+f"(d[3])
        : "r"(a0), "r"(a1), "r"(a2), "r"(a3), "r"(b0), "r"(b1));
}

// ---------------------------------------------------------------------------
// Kernel 0: expand relative-position bias table -> [8][50][50], zero row/col 0
// ---------------------------------------------------------------------------
__global__ void bias_expand_kernel(const float* __restrict__ bt, const int* __restrict__ ridx) {
    int i = blockIdx.x * 256 + threadIdx.x;
    if (i >= NUM_HEADS * NTOK * NTOK) return;
    int h = i / (NTOK * NTOK);
    int rem = i - h * NTOK * NTOK;
    int r = rem / NTOK;
    int c = rem - r * NTOK;
    float v = 0.f;
    if (r > 0 && c > 0) {
        int idx = ridx[(r - 1) * 49 + (c - 1)];
        v = bt[idx * NUM_HEADS + h];
    }
    g_bias[i] = v;
}

// ---------------------------------------------------------------------------
// Kernels 1 & 3: tf32 GEMM  C[M, N] = A[M,256] @ W[N,256]^T + bias
// BM=64, BN=128, BK=16; 128 threads = 4 warps (2m x 2n), warp tile 32x64.
// Fragment-major shared layout: frag loads are single LDS.128, conflict-free
// (lane swizzle ls = lane ^ ((lane>>3)&3), tile stride 132 words).
//   A tile: As[buf][ (mt*2+ks2) ][132]:  word = t*132 + lane_s*4 + kh*2 + mbit
//           (reg order within 16B: (k_lo,m_lo),(k_lo,m_hi),(k_hi,m_lo),(k_hi,m_hi))
//   B tile: Bs[buf][ nt ][132]:          word = nt*132 + lane_s*4 + k4
// ---------------------------------------------------------------------------
__global__ __launch_bounds__(128) void gemm_tf32_kernel(
    const float* __restrict__ A, const float* __restrict__ W,
    const float* __restrict__ bias, float* __restrict__ out, int epi)
{
    if (epi == 1) A = g_att;

    __shared__ uint32_t As[2][8 * 132];    // 8 (mt,ks2) tiles
    __shared__ uint32_t Bs[2][16 * 132];   // 16 nt tiles

    const int tid = threadIdx.x;
    const int lane = tid & 31;
    const int warp = tid >> 5;
    const int wm = warp >> 1, wn = warp & 1;
    const int bm = blockIdx.y, bn = blockIdx.x;

    // --- A loader mapping: thread -> rows (r0, r0+8), k-quad q ---
    const int g = tid >> 2, q = tid & 3;
    const int a_mt = g >> 3, a_m7 = g & 7;
    const int a_ks2 = q >> 1, a_kh = q & 1;
    const float* Ag0 = A + ((size_t)(bm * 64 + a_mt * 16 + a_m7)) * 256 + q * 4;
    const float* Ag1 = Ag0 + 8 * 256;
    int a_saddr[4];
#pragma unroll
    for (int j = 0; j < 4; j++) {
        int lsd = a_m7 * 4 + (j ^ ((a_m7 >> 1) & 3));
        a_saddr[j] = (a_mt * 2 + a_ks2) * 132 + lsd * 4 + a_kh * 2;
    }

    // --- B loader mapping: thread -> one W row (16 k) ---
    const float* Wg = W + ((size_t)(bn * 128 + tid)) * 256;
    const int b_nt = tid >> 3, b_n7 = tid & 7;
    int b_saddr[4];
#pragma unroll
    for (int j = 0; j < 4; j++) {
        int lsd = b_n7 * 4 + (j ^ ((b_n7 >> 1) & 3));
        b_saddr[j] = b_nt * 132 + lsd * 4;
    }

    const int ls = lane ^ ((lane >> 3) & 3);

    float acc[2][8][4];
#pragma unroll
    for (int i = 0; i < 2; i++)
#pragma unroll
        for (int j = 0; j < 8; j++)
#pragma unroll
            for (int r = 0; r < 4; r++) acc[i][j][r] = 0.f;

    // prologue: global load kt=0, convert+store into buf 0
    float a0r[4], a1r[4], brr[16];
    {
        float4 t0 = *(const float4*)Ag0;
        float4 t1 = *(const float4*)Ag1;
        a0r[0] = t0.x; a0r[1] = t0.y; a0r[2] = t0.z; a0r[3] = t0.w;
        a1r[0] = t1.x; a1r[1] = t1.y; a1r[2] = t1.z; a1r[3] = t1.w;
#pragma unroll
        for (int f = 0; f < 4; f++) {
            float4 t = *(const float4*)(Wg + f * 4);
            brr[f * 4 + 0] = t.x; brr[f * 4 + 1] = t.y; brr[f * 4 + 2] = t.z; brr[f * 4 + 3] = t.w;
        }
#pragma unroll
        for (int j = 0; j < 4; j++) {
            *(uint2*)&As[0][a_saddr[j]] = make_uint2(f2tf32(a0r[j]), f2tf32(a1r[j]));
            *(uint4*)&Bs[0][b_saddr[j]] =
                make_uint4(f2tf32(brr[j]), f2tf32(brr[j + 4]), f2tf32(brr[j + 8]), f2tf32(brr[j + 12]));
        }
    }

    for (int kt = 0; kt < 16; kt++) {
        __syncthreads();
        const int cur = kt & 1;

        // prefetch next k-tile from global
        if (kt < 15) {
            const int ko = (kt + 1) * 16;
            float4 t0 = *(const float4*)(Ag0 + ko);
            float4 t1 = *(const float4*)(Ag1 + ko);
            a0r[0] = t0.x; a0r[1] = t0.y; a0r[2] = t0.z; a0r[3] = t0.w;
            a1r[0] = t1.x; a1r[1] = t1.y; a1r[2] = t1.z; a1r[3] = t1.w;
#pragma unroll
            for (int f = 0; f < 4; f++) {
                float4 t = *(const float4*)(Wg + ko + f * 4);
                brr[f * 4 + 0] = t.x; brr[f * 4 + 1] = t.y; brr[f * 4 + 2] = t.z; brr[f * 4 + 3] = t.w;
            }
        }

        // B fragments for both k-steps: one LDS.128 per n8 tile
        uint4 bf[8];
#pragma unroll
        for (int tn = 0; tn < 8; tn++)
            bf[tn] = *(const uint4*)&Bs[cur][(wn * 8 + tn) * 132 + ls * 4];

#pragma unroll
        for (int ks2 = 0; ks2 < 2; ks2++) {
            uint4 af[2];
#pragma unroll
            for (int tm = 0; tm < 2; tm++)
                af[tm] = *(const uint4*)&As[cur][((wm * 2 + tm) * 2 + ks2) * 132 + ls * 4];
#pragma unroll
            for (int tm = 0; tm < 2; tm++)
#pragma unroll
                for (int tn = 0; tn < 8; tn++) {
                    uint32_t b0 = ks2 ? bf[tn].z : bf[tn].x;
                    uint32_t b1 = ks2 ? bf[tn].w : bf[tn].y;
                    // reg order in af: x=(k_lo,m_lo) y=(k_lo,m_hi) z=(k_hi,m_lo) w=(k_hi,m_hi)
                    mma_tf32(acc[tm][tn], af[tm].x, af[tm].y, af[tm].z, af[tm].w, b0, b1);
                }
        }

        if (kt < 15) {
            const int nxt = cur ^ 1;
#pragma unroll
            for (int j = 0; j < 4; j++) {
                *(uint2*)&As[nxt][a_saddr[j]] = make_uint2(f2tf32(a0r[j]), f2tf32(a1r[j]));
                *(uint4*)&Bs[nxt][b_saddr[j]] =
                    make_uint4(f2tf32(brr[j]), f2tf32(brr[j + 4]), f2tf32(brr[j + 8]), f2tf32(brr[j + 12]));
            }
        }
    }

    const float scale = 0.17677669529663687f;  // 32^-0.5
#pragma unroll
    for (int tm = 0; tm < 2; tm++)
#pragma unroll
        for (int tn = 0; tn < 8; tn++) {
            int m_g = bm * 64 + wm * 32 + tm * 16 + (lane >> 2);
            int n_g = bn * 128 + wn * 64 + tn * 8 + 2 * (lane & 3);
#pragma unroll
            for (int hf = 0; hf < 2; hf++) {
                int mm = m_g + hf * 8;
                float v0 = acc[tm][tn][hf * 2 + 0] + bias[n_g];
                float v1 = acc[tm][tn][hf * 2 + 1] + bias[n_g + 1];
                if (epi == 0) {
                    int which = n_g >> 8;
                    int rcol = n_g & 255;
                    int h = rcol >> 5, d = rcol & 31;
                    if (which == 0) { v0 *= scale; v1 *= scale; }
                    int b = mm / NTOK;
                    int t = mm - b * NTOK;
                    size_t idx = ((size_t)which * NWIN * NUM_HEADS + (size_t)b * NUM_HEADS + h)
                                     * (NTOK * HEADDIM)
                                 + t * HEADDIM + d;
                    *(float2*)(g_qkv + idx) = make_float2(v0, v1);
                } else {
                    *(float2*)(out + (size_t)mm * CDIM + n_g) = make_float2(v0, v1);
                }
            }
        }
}

// ---------------------------------------------------------------------------
// Kernel 2: fused attention per (window, head). 128 threads / block.
// ---------------------------------------------------------------------------
__global__ __launch_bounds__(128) void attn_kernel() {
    const int bh = blockIdx.x;
    const int b = bh >> 3, h = bh & 7;

    __shared__ float qs[50 * 36];
    __shared__ float ks2[50 * 36];
    __shared__ float vs[50 * 36];
    __shared__ float Ps[50 * 52];
    __shared__ float redmax[50 * 2], redsum[50 * 2], rinv[50];

    const int tid = threadIdx.x;
    const size_t strideWH = (size_t)NWIN * NUM_HEADS * NTOK * HEADDIM;
    const float* qg = g_qkv + ((size_t)b * NUM_HEADS + h) * (NTOK * HEADDIM);
    const float* kg = qg + strideWH;
    const float* vg = kg + strideWH;

    for (int i = tid; i < 400; i += 128) {  // 50*32/4 float4s per array
        int r = i >> 3, c = (i & 7) * 4;
        *(float4*)(qs + r * 36 + c) = *(const float4*)(qg + i * 4);
        *(float4*)(ks2 + r * 36 + c) = *(const float4*)(kg + i * 4);
        *(float4*)(vs + r * 36 + c) = *(const float4*)(vg + i * 4);
    }
    const float* bg = g_bias + h * (NTOK * NTOK);
    for (int i = tid; i < NTOK * NTOK; i += 128) {
        int r = i / NTOK, c = i - r * NTOK;
        Ps[r * 52 + c] = bg[i];
    }
    __syncthreads();

    const int r = tid >> 1;
    const int half = tid & 1;
    float sv[25];
    if (r < 50) {
        float4 q4[8];
#pragma unroll
        for (int kk = 0; kk < 8; kk++) q4[kk] = *(const float4*)(qs + r * 36 + kk * 4);
        const int cbase = half * 25;
        float smax = -1e30f;
#pragma unroll
        for (int c = 0; c < 25; c++) {
            const float* kr = ks2 + (cbase + c) * 36;
            float a = Ps[r * 52 + cbase + c];  // bias
#pragma unroll
            for (int kk = 0; kk < 8; kk++) {
                float4 k4 = *(const float4*)(kr + kk * 4);
                a += q4[kk].x * k4.x + q4[kk].y * k4.y + q4[kk].z * k4.z + q4[kk].w * k4.w;
            }
            sv[c] = a;
            smax = fmaxf(smax, a);
        }
        redmax[r * 2 + half] = smax;
    }
    __syncthreads();
    if (r < 50) {
        float m = fmaxf(redmax[r * 2], redmax[r * 2 + 1]);
        const int cbase = half * 25;
        float s = 0.f;
#pragma unroll
        for (int c = 0; c < 25; c++) {
            float e = __expf(sv[c] - m);
            Ps[r * 52 + cbase + c] = e;
            s += e;
        }
        redsum[r * 2 + half] = s;
    }
    __syncthreads();
    if (tid < 50) rinv[tid] = 1.f / (redsum[tid * 2] + redsum[tid * 2 + 1]);
    __syncthreads();

    // PV: thread = (row-group rg, d-quad d4); float4 V loads, float4 stores
    const int d4 = tid & 7;
    const int rg = tid >> 3;
    float* ogb = g_att + (size_t)b * NTOK * CDIM + h * HEADDIM + d4 * 4;
    for (int rr = rg; rr < 50; rr += 16) {
        float ax = 0.f, ay = 0.f, az = 0.f, aw = 0.f;
        const float* pr = Ps + rr * 52;
#pragma unroll
        for (int c = 0; c < 50; c++) {
            float p = pr[c];
            float4 v = *(const float4*)(vs + c * 36 + d4 * 4);
            ax += p * v.x; ay += p * v.y; az += p * v.z; aw += p * v.w;
        }
        float rv = rinv[rr];
        *(float4*)(ogb + (size_t)rr * CDIM) = make_float4(ax * rv, ay * rv, az * rv, aw * rv);
    }
}

// ---------------------------------------------------------------------------
extern "C" void kernel_launch(void* const* d_in, const int* in_sizes, int n_in,
                              void* d_out, int out_size) {
    const float* x = (const float*)d_in[0];
    const float* qkv_w = (const float*)d_in[1];
    const float* qkv_b = (const float*)d_in[2];
    const float* proj_w = (const float*)d_in[3];
    const float* proj_b = (const float*)d_in[4];
    const float* bias_table = (const float*)d_in[5];
    const int* rel_idx = (const int*)d_in[6];
    float* out = (float*)d_out;

    (void)in_sizes; (void)n_in; (void)out_size;

    bias_expand_kernel<<<(NUM_HEADS * NTOK * NTOK + 255) / 256, 256>>>(bias_table, rel_idx);
    gemm_tf32_kernel<<<dim3(768 / 128, (NWIN * NTOK) / 64), 128>>>(x, qkv_w, qkv_b, nullptr, 0);
    attn_kernel<<<NWIN * NUM_HEADS, 128>>>();
    gemm_tf32_kernel<<<dim3(CDIM / 128, (NWIN * NTOK) / 64), 128>>>(nullptr, proj_w, proj_b, out, 1);
}

// round 13
// speedup vs baseline: 1.5062x; 1.5062x over previous
#include <cuda_runtime.h>
#include <cstdint>
#include <cstddef>

#define NUM_HEADS 8
#define NTOK 50
#define HEADDIM 32
#define NWIN 2048
#define CDIM 256
#define MTOT (NWIN * NTOK)  // 102400

// Scratch (allocation-free rule: __device__ globals)
__device__ float g_qkv[3ULL * NWIN * NUM_HEADS * NTOK * HEADDIM];  // [which][b][h][t][d]
__device__ float g_xs[(size_t)MTOT * CDIM];    // x as tf32 SW128 slab image [1600][8][64][32]
__device__ float g_atts[(size_t)MTOT * CDIM];  // attn out, same image format
__device__ float g_wq[768 * 256];              // qkv_w image [6][8][128][32]
__device__ float g_wp[256 * 256];              // proj_w image [2][8][128][32]
__device__ float g_bias[NUM_HEADS * NTOK * NTOK];

__device__ __forceinline__ uint32_t f2tf32(float f) {
    uint32_t r;
    asm("cvt.rna.tf32.f32 %0, %1;" : "=r"(r) : "f"(f));
    return r;
}
__device__ __forceinline__ float tfr(float f) { return __uint_as_float(f2tf32(f)); }

__device__ __forceinline__ uint32_t smem_u32(const void* p) {
    uint32_t a;
    asm("{ .reg .u64 t; cvta.to.shared.u64 t, %1; cvt.u32.u64 %0, t; }" : "=r"(a) : "l"(p));
    return a;
}

__device__ __forceinline__ void mma_tf32(float d[4],
                                         uint32_t a0, uint32_t a1, uint32_t a2, uint32_t a3,
                                         uint32_t b0, uint32_t b1) {
    asm volatile(
        "mma.sync.aligned.m16n8k8.row.col.f32.tf32.tf32.f32 "
        "{%0,%1,%2,%3}, {%4,%5,%6,%7}, {%8,%9}, {%0,%1,%2,%3};\n"
        : "+f"(d[0]), "+f"(d[1]), "+f"(d[2]), "+f"(d[3])
        : "r"(a0), "r"(a1), "r"(a2), "r"(a3), "r"(b0), "r"(b1));
}

__device__ __forceinline__ void cp16(uint32_t dst, const void* src) {
    asm volatile("cp.async.cg.shared.global [%0], [%1], 16;" :: "r"(dst), "l"(src));
}
#define CP_COMMIT() asm volatile("cp.async.commit_group;")
template <int N>
__device__ __forceinline__ void cp_wait() {
    asm volatile("cp.async.wait_group %0;" :: "n"(N));
}

// ---------------------------------------------------------------------------
// Kernel 0: expand relative-position bias table -> [8][50][50], zero row/col 0
// ---------------------------------------------------------------------------
__global__ void bias_expand_kernel(const float* __restrict__ bt, const int* __restrict__ ridx) {
    int i = blockIdx.x * 256 + threadIdx.x;
    if (i >= NUM_HEADS * NTOK * NTOK) return;
    int h = i / (NTOK * NTOK);
    int rem = i - h * NTOK * NTOK;
    int r = rem / NTOK;
    int c = rem - r * NTOK;
    float v = 0.f;
    if (r > 0 && c > 0) {
        int idx = ridx[(r - 1) * 49 + (c - 1)];
        v = bt[idx * NUM_HEADS + h];
    }
    g_bias[i] = v;
}

// ---------------------------------------------------------------------------
// Conversion kernels: build tf32 SW128 slab images.
// A-image (64-row tiles):  dst[(m>>6)*8 + slab][ (m&63)*32 + swz ]
// W-image (128-row tiles): dst[(n>>7)*8 + slab][ (n&127)*32 + swz ]
// swz: byte-in-row (j*16) ^ ((row&7)<<4)
// ---------------------------------------------------------------------------
__global__ void xconv_kernel(const float* __restrict__ x) {
    size_t idx = (size_t)blockIdx.x * 256 + threadIdx.x;  // float4 index
    if (idx >= (size_t)MTOT * 64) return;
    int m = (int)(idx >> 6);
    int c4 = (int)(idx & 63);
    int slab = c4 >> 3, j = c4 & 7;
    float4 v = *(const float4*)(x + (size_t)m * 256 + c4 * 4);
    uint32_t boff = ((uint32_t)(j * 16)) ^ (((uint32_t)m & 7u) << 4);
    float* dst = g_xs + ((size_t)(m >> 6) * 8 + slab) * 2048 + (size_t)(m & 63) * 32 + (boff >> 2);
    *(float4*)dst = make_float4(tfr(v.x), tfr(v.y), tfr(v.z), tfr(v.w));
}

__global__ void wconv_kernel(const float* __restrict__ w, int which, int nrows) {
    int idx = blockIdx.x * 256 + threadIdx.x;
    if (idx >= nrows * 64) return;
    int n = idx >> 6, c4 = idx & 63;
    int slab = c4 >> 3, j = c4 & 7;
    float4 v = *(const float4*)(w + (size_t)n * 256 + c4 * 4);
    uint32_t boff = ((uint32_t)(j * 16)) ^ (((uint32_t)n & 7u) << 4);
    float* base = which ? g_wp : g_wq;
    float* dst = base + ((size_t)(n >> 7) * 8 + slab) * 4096 + (size_t)(n & 127) * 32 + (boff >> 2);
    *(float4*)dst = make_float4(tfr(v.x), tfr(v.y), tfr(v.z), tfr(v.w));
}

// ---------------------------------------------------------------------------
// GEMM: C[M,N] = A[M,256] @ W[N,256]^T + bias.  Operands pre-converted tf32
// SW128 images; cp.async double-buffered; BM=64, BN=128, 4 warps (2m x 2n),
// warp tile 32x64, mma m16n8k8. epi0: QKV scatter (q scaled); epi1: out.
// ---------------------------------------------------------------------------
__global__ __launch_bounds__(128) void gemm_cp_kernel(
    const float* __restrict__ bias, float* __restrict__ out, int epi)
{
    const float* Aimg = epi ? g_atts : g_xs;
    const float* Bimg = epi ? g_wp : g_wq;

    __shared__ __align__(16) float sm[2][6144];  // [A 2048 floats][B 4096 floats]

    const int tid = threadIdx.x;
    const int lane = tid & 31;
    const int warp = tid >> 5;
    const int wm = warp >> 1, wn = warp & 1;
    const int bm = blockIdx.y, bn = blockIdx.x;

    const float* Abase = Aimg + (size_t)bm * 8 * 2048;
    const float* Bbase = Bimg + (size_t)bn * 8 * 4096;
    const uint32_t sbuf[2] = { smem_u32(sm[0]), smem_u32(sm[1]) };

    float acc[2][8][4];
#pragma unroll
    for (int i = 0; i < 2; i++)
#pragma unroll
        for (int j = 0; j < 8; j++)
#pragma unroll
            for (int r = 0; r < 4; r++) acc[i][j][r] = 0.f;

    auto issue = [&](int s, int buf) {
        const float* As = Abase + s * 2048;
        const float* Bs = Bbase + s * 4096;
        uint32_t sa = sbuf[buf];
#pragma unroll
        for (int c = 0; c < 4; c++)
            cp16(sa + (uint32_t)(c * 128 + tid) * 16u, As + (c * 128 + tid) * 4);
#pragma unroll
        for (int c = 0; c < 8; c++)
            cp16(sa + 8192u + (uint32_t)(c * 128 + tid) * 16u, Bs + (c * 128 + tid) * 4);
        CP_COMMIT();
    };

    issue(0, 0);
    issue(1, 1);

#pragma unroll
    for (int s = 0; s < 8; s++) {
        if (s < 7) cp_wait<1>(); else cp_wait<0>();
        __syncthreads();
        const float* A = sm[s & 1];
        const float* B = A + 2048;

#pragma unroll
        for (int ks = 0; ks < 4; ks++) {
            const uint32_t klo = (uint32_t)(ks * 32 + (lane & 3) * 4);  // byte-in-row
            uint32_t bf[8][2];
#pragma unroll
            for (int tn = 0; tn < 8; tn++) {
                int nr = wn * 64 + tn * 8 + (lane >> 2);
                uint32_t sw = ((uint32_t)nr & 7u) << 4;
                bf[tn][0] = __float_as_uint(B[nr * 32 + ((klo ^ sw) >> 2)]);
                bf[tn][1] = __float_as_uint(B[nr * 32 + (((klo + 16u) ^ sw) >> 2)]);
            }
#pragma unroll
            for (int tm = 0; tm < 2; tm++) {
                int r = wm * 32 + tm * 16 + (lane >> 2);
                uint32_t sw = ((uint32_t)r & 7u) << 4;  // (r+8)&7 == r&7
                uint32_t o0 = (klo ^ sw) >> 2, o1 = ((klo + 16u) ^ sw) >> 2;
                uint32_t a0 = __float_as_uint(A[r * 32 + o0]);
                uint32_t a1 = __float_as_uint(A[(r + 8) * 32 + o0]);
                uint32_t a2 = __float_as_uint(A[r * 32 + o1]);
                uint32_t a3 = __float_as_uint(A[(r + 8) * 32 + o1]);
#pragma unroll
                for (int tn = 0; tn < 8; tn++)
                    mma_tf32(acc[tm][tn], a0, a1, a2, a3, bf[tn][0], bf[tn][1]);
            }
        }
        __syncthreads();
        if (s + 2 < 8) issue(s + 2, s & 1);
    }

    const float scale = 0.17677669529663687f;  // 32^-0.5
#pragma unroll
    for (int tm = 0; tm < 2; tm++)
#pragma unroll
        for (int tn = 0; tn < 8; tn++) {
            int m_g = bm * 64 + wm * 32 + tm * 16 + (lane >> 2);
            int n_g = bn * 128 + wn * 64 + tn * 8 + 2 * (lane & 3);
#pragma unroll
            for (int hf = 0; hf < 2; hf++) {
                int mm = m_g + hf * 8;
                float v0 = acc[tm][tn][hf * 2 + 0] + __ldg(bias + n_g);
                float v1 = acc[tm][tn][hf * 2 + 1] + __ldg(bias + n_g + 1);
                if (epi == 0) {
                    int which = n_g >> 8;
                    int rcol = n_g & 255;
                    int h = rcol >> 5, d = rcol & 31;
                    if (which == 0) { v0 *= scale; v1 *= scale; }
                    int b = mm / NTOK;
                    int t = mm - b * NTOK;
                    size_t idx = ((size_t)which * NWIN * NUM_HEADS + (size_t)b * NUM_HEADS + h)
                                     * (NTOK * HEADDIM)
                                 + t * HEADDIM + d;
                    *(float2*)(g_qkv + idx) = make_float2(v0, v1);
                } else {
                    *(float2*)(out + (size_t)mm * CDIM + n_g) = make_float2(v0, v1);
                }
            }
        }
}

// ---------------------------------------------------------------------------
// Kernel 2: fused attention per (window, head). 128 threads / block.
// Output written tf32-rounded into the SW128 slab image g_atts (head = slab).
// ---------------------------------------------------------------------------
__global__ __launch_bounds__(128) void attn_kernel() {
    const int bh = blockIdx.x;
    const int b = bh >> 3, h = bh & 7;

    __shared__ float qs[50 * 36];
    __shared__ float ks2[50 * 36];
    __shared__ float vs[50 * 36];
    __shared__ float Ps[50 * 52];
    __shared__ float redmax[50 * 2], redsum[50 * 2], rinv[50];

    const int tid = threadIdx.x;
    const size_t strideWH = (size_t)NWIN * NUM_HEADS * NTOK * HEADDIM;
    const float* qg = g_qkv + ((size_t)b * NUM_HEADS + h) * (NTOK * HEADDIM);
    const float* kg = qg + strideWH;
    const float* vg = kg + strideWH;

    for (int i = tid; i < 400; i += 128) {  // 50*32/4 float4s per array
        int r = i >> 3, c = (i & 7) * 4;
        *(float4*)(qs + r * 36 + c) = *(const float4*)(qg + i * 4);
        *(float4*)(ks2 + r * 36 + c) = *(const float4*)(kg + i * 4);
        *(float4*)(vs + r * 36 + c) = *(const float4*)(vg + i * 4);
    }
    const float* bg = g_bias + h * (NTOK * NTOK);
    for (int i = tid; i < NTOK * NTOK; i += 128) {
        int r = i / NTOK, c = i - r * NTOK;
        Ps[r * 52 + c] = bg[i];
    }
    __syncthreads();

    const int r = tid >> 1;
    const int half = tid & 1;
    float sv[25];
    if (r < 50) {
        float4 q4[8];
#pragma unroll
        for (int kk = 0; kk < 8; kk++) q4[kk] = *(const float4*)(qs + r * 36 + kk * 4);
        const int cbase = half * 25;
        float smax = -1e30f;
#pragma unroll
        for (int c = 0; c < 25; c++) {
            const float* kr = ks2 + (cbase + c) * 36;
            float a = Ps[r * 52 + cbase + c];  // bias
#pragma unroll
            for (int kk = 0; kk < 8; kk++) {
                float4 k4 = *(const float4*)(kr + kk * 4);
                a += q4[kk].x * k4.x + q4[kk].y * k4.y + q4[kk].z * k4.z + q4[kk].w * k4.w;
            }
            sv[c] = a;
            smax = fmaxf(smax, a);
        }
        redmax[r * 2 + half] = smax;
    }
    __syncthreads();
    if (r < 50) {
        float m = fmaxf(redmax[r * 2], redmax[r * 2 + 1]);
        const int cbase = half * 25;
        float s = 0.f;
#pragma unroll
        for (int c = 0; c < 25; c++) {
            float e = __expf(sv[c] - m);
            Ps[r * 52 + cbase + c] = e;
            s += e;
        }
        redsum[r * 2 + half] = s;
    }
    __syncthreads();
    if (tid < 50) rinv[tid] = 1.f / (redsum[tid * 2] + redsum[tid * 2 + 1]);
    __syncthreads();

    // PV: thread = (row-group rg, d-quad d4); write tf32 SW128 image
    const int d4 = tid & 7;
    const int rg = tid >> 3;
    for (int rr = rg; rr < 50; rr += 16) {
        float ax = 0.f, ay = 0.f, az = 0.f, aw = 0.f;
        const float* pr = Ps + rr * 52;
#pragma unroll
        for (int c = 0; c < 50; c++) {
            float p = pr[c];
            float4 v = *(const float4*)(vs + c * 36 + d4 * 4);
            ax += p * v.x; ay += p * v.y; az += p * v.z; aw += p * v.w;
        }
        float rv = rinv[rr];
        int m = b * NTOK + rr;
        uint32_t boff = ((uint32_t)(d4 * 16)) ^ (((uint32_t)m & 7u) << 4);
        float* dst = g_atts + ((size_t)(m >> 6) * 8 + h) * 2048 + (size_t)(m & 63) * 32 + (boff >> 2);
        *(float4*)dst = make_float4(tfr(ax * rv), tfr(ay * rv), tfr(az * rv), tfr(aw * rv));
    }
}

// ---------------------------------------------------------------------------
extern "C" void kernel_launch(void* const* d_in, const int* in_sizes, int n_in,
                              void* d_out, int out_size) {
    const float* x = (const float*)d_in[0];
    const float* qkv_w = (const float*)d_in[1];
    const float* qkv_b = (const float*)d_in[2];
    const float* proj_w = (const float*)d_in[3];
    const float* proj_b = (const float*)d_in[4];
    const float* bias_table = (const float*)d_in[5];
    const int* rel_idx = (const int*)d_in[6];
    float* out = (float*)d_out;

    (void)in_sizes; (void)n_in; (void)out_size;

    bias_expand_kernel<<<(NUM_HEADS * NTOK * NTOK + 255) / 256, 256>>>(bias_table, rel_idx);
    wconv_kernel<<<(768 * 64 + 255) / 256, 256>>>(qkv_w, 0, 768);
    wconv_kernel<<<(256 * 64 + 255) / 256, 256>>>(proj_w, 1, 256);
    xconv_kernel<<<(int)(((size_t)MTOT * 64 + 255) / 256), 256>>>(x);
    // QKV: M tiles (64 rows) = 1600, N tiles (128 cols) = 6
    gemm_cp_kernel<<<dim3(6, 1600), 128>>>(qkv_b, nullptr, 0);
    attn_kernel<<<NWIN * NUM_HEADS, 128>>>();
    // proj: N tiles = 2
    gemm_cp_kernel<<<dim3(2, 1600), 128>>>(proj_b, out, 1);
}

// round 14
// speedup vs baseline: 2.1152x; 1.4044x over previous
#include <cuda_runtime.h>
#include <cstdint>
#include <cstddef>

#define NUM_HEADS 8
#define NTOK 50
#define HEADDIM 32
#define NWIN 2048
#define CDIM 256
#define MTOT (NWIN * NTOK)  // 102400

// Scratch (allocation-free rule: __device__ globals)
__device__ float g_qkv[3ULL * NWIN * NUM_HEADS * NTOK * HEADDIM];  // [which][b][h][t][d]
__device__ float g_xs[(size_t)MTOT * CDIM];    // x as tf32 SW128 slab image [1600][8][64][32]
__device__ float g_atts[(size_t)MTOT * CDIM];  // attn out, same image format
__device__ float g_wq[768 * 256];              // qkv_w image [6][8][128][32]
__device__ float g_wp[256 * 256];              // proj_w image [2][8][128][32]
__device__ float g_bias[NUM_HEADS * NTOK * NTOK];

__device__ __forceinline__ uint32_t f2tf32(float f) {
    uint32_t r;
    asm("cvt.rna.tf32.f32 %0, %1;" : "=r"(r) : "f"(f));
    return r;
}
__device__ __forceinline__ float tfr(float f) { return __uint_as_float(f2tf32(f)); }

__device__ __forceinline__ uint32_t smem_u32(const void* p) {
    uint32_t a;
    asm("{ .reg .u64 t; cvta.to.shared.u64 t, %1; cvt.u32.u64 %0, t; }" : "=r"(a) : "l"(p));
    return a;
}

__device__ __forceinline__ void mma_tf32(float d[4],
                                         uint32_t a0, uint32_t a1, uint32_t a2, uint32_t a3,
                                         uint32_t b0, uint32_t b1) {
    asm volatile(
        "mma.sync.aligned.m16n8k8.row.col.f32.tf32.tf32.f32 "
        "{%0,%1,%2,%3}, {%4,%5,%6,%7}, {%8,%9}, {%0,%1,%2,%3};\n"
        : "+f"(d[0]), "+f"(d[1]), "+f"(d[2]), "+f"(d[3])
        : "r"(a0), "r"(a1), "r"(a2), "r"(a3), "r"(b0), "r"(b1));
}
__device__ __forceinline__ void mma_tf32f(float d[4],
                                          float a0, float a1, float a2, float a3,
                                          float b0, float b1) {
    mma_tf32(d, __float_as_uint(a0), __float_as_uint(a1), __float_as_uint(a2),
             __float_as_uint(a3), __float_as_uint(b0), __float_as_uint(b1));
}

__device__ __forceinline__ void cp16(uint32_t dst, const void* src) {
    asm volatile("cp.async.cg.shared.global [%0], [%1], 16;" :: "r"(dst), "l"(src));
}
#define CP_COMMIT() asm volatile("cp.async.commit_group;")
template <int N>
__device__ __forceinline__ void cp_wait() {
    asm volatile("cp.async.wait_group %0;" :: "n"(N));
}

// ---------------------------------------------------------------------------
// Kernel 0: expand relative-position bias table -> [8][50][50], zero row/col 0
// ---------------------------------------------------------------------------
__global__ void bias_expand_kernel(const float* __restrict__ bt, const int* __restrict__ ridx) {
    int i = blockIdx.x * 256 + threadIdx.x;
    if (i >= NUM_HEADS * NTOK * NTOK) return;
    int h = i / (NTOK * NTOK);
    int rem = i - h * NTOK * NTOK;
    int r = rem / NTOK;
    int c = rem - r * NTOK;
    float v = 0.f;
    if (r > 0 && c > 0) {
        int idx = ridx[(r - 1) * 49 + (c - 1)];
        v = bt[idx * NUM_HEADS + h];
    }
    g_bias[i] = v;
}

// ---------------------------------------------------------------------------
// Conversion kernels: build tf32 SW128 slab images.
// ---------------------------------------------------------------------------
__global__ void xconv_kernel(const float* __restrict__ x) {
    size_t idx = (size_t)blockIdx.x * 256 + threadIdx.x;  // float4 index
    if (idx >= (size_t)MTOT * 64) return;
    int m = (int)(idx >> 6);
    int c4 = (int)(idx & 63);
    int slab = c4 >> 3, j = c4 & 7;
    float4 v = *(const float4*)(x + (size_t)m * 256 + c4 * 4);
    uint32_t boff = ((uint32_t)(j * 16)) ^ (((uint32_t)m & 7u) << 4);
    float* dst = g_xs + ((size_t)(m >> 6) * 8 + slab) * 2048 + (size_t)(m & 63) * 32 + (boff >> 2);
    *(float4*)dst = make_float4(tfr(v.x), tfr(v.y), tfr(v.z), tfr(v.w));
}

__global__ void wconv_kernel(const float* __restrict__ w, int which, int nrows) {
    int idx = blockIdx.x * 256 + threadIdx.x;
    if (idx >= nrows * 64) return;
    int n = idx >> 6, c4 = idx & 63;
    int slab = c4 >> 3, j = c4 & 7;
    float4 v = *(const float4*)(w + (size_t)n * 256 + c4 * 4);
    uint32_t boff = ((uint32_t)(j * 16)) ^ (((uint32_t)n & 7u) << 4);
    float* base = which ? g_wp : g_wq;
    float* dst = base + ((size_t)(n >> 7) * 8 + slab) * 4096 + (size_t)(n & 127) * 32 + (boff >> 2);
    *(float4*)dst = make_float4(tfr(v.x), tfr(v.y), tfr(v.z), tfr(v.w));
}

// ---------------------------------------------------------------------------
// GEMM (unchanged, measured good): cp.async double-buffered tf32 MMA.
// ---------------------------------------------------------------------------
__global__ __launch_bounds__(128) void gemm_cp_kernel(
    const float* __restrict__ bias, float* __restrict__ out, int epi)
{
    const float* Aimg = epi ? g_atts : g_xs;
    const float* Bimg = epi ? g_wp : g_wq;

    __shared__ __align__(16) float sm[2][6144];  // [A 2048 floats][B 4096 floats]

    const int tid = threadIdx.x;
    const int lane = tid & 31;
    const int warp = tid >> 5;
    const int wm = warp >> 1, wn = warp & 1;
    const int bm = blockIdx.y, bn = blockIdx.x;

    const float* Abase = Aimg + (size_t)bm * 8 * 2048;
    const float* Bbase = Bimg + (size_t)bn * 8 * 4096;
    const uint32_t sbuf[2] = { smem_u32(sm[0]), smem_u32(sm[1]) };

    float acc[2][8][4];
#pragma unroll
    for (int i = 0; i < 2; i++)
#pragma unroll
        for (int j = 0; j < 8; j++)
#pragma unroll
            for (int r = 0; r < 4; r++) acc[i][j][r] = 0.f;

    auto issue = [&](int s, int buf) {
        const float* As = Abase + s * 2048;
        const float* Bs = Bbase + s * 4096;
        uint32_t sa = sbuf[buf];
#pragma unroll
        for (int c = 0; c < 4; c++)
            cp16(sa + (uint32_t)(c * 128 + tid) * 16u, As + (c * 128 + tid) * 4);
#pragma unroll
        for (int c = 0; c < 8; c++)
            cp16(sa + 8192u + (uint32_t)(c * 128 + tid) * 16u, Bs + (c * 128 + tid) * 4);
        CP_COMMIT();
    };

    issue(0, 0);
    issue(1, 1);

#pragma unroll
    for (int s = 0; s < 8; s++) {
        if (s < 7) cp_wait<1>(); else cp_wait<0>();
        __syncthreads();
        const float* A = sm[s & 1];
        const float* B = A + 2048;

#pragma unroll
        for (int ks = 0; ks < 4; ks++) {
            const uint32_t klo = (uint32_t)(ks * 32 + (lane & 3) * 4);  // byte-in-row
            uint32_t bf[8][2];
#pragma unroll
            for (int tn = 0; tn < 8; tn++) {
                int nr = wn * 64 + tn * 8 + (lane >> 2);
                uint32_t sw = ((uint32_t)nr & 7u) << 4;
                bf[tn][0] = __float_as_uint(B[nr * 32 + ((klo ^ sw) >> 2)]);
                bf[tn][1] = __float_as_uint(B[nr * 32 + (((klo + 16u) ^ sw) >> 2)]);
            }
#pragma unroll
            for (int tm = 0; tm < 2; tm++) {
                int r = wm * 32 + tm * 16 + (lane >> 2);
                uint32_t sw = ((uint32_t)r & 7u) << 4;  // (r+8)&7 == r&7
                uint32_t o0 = (klo ^ sw) >> 2, o1 = ((klo + 16u) ^ sw) >> 2;
                uint32_t a0 = __float_as_uint(A[r * 32 + o0]);
                uint32_t a1 = __float_as_uint(A[(r + 8) * 32 + o0]);
                uint32_t a2 = __float_as_uint(A[r * 32 + o1]);
                uint32_t a3 = __float_as_uint(A[(r + 8) * 32 + o1]);
#pragma unroll
                for (int tn = 0; tn < 8; tn++)
                    mma_tf32(acc[tm][tn], a0, a1, a2, a3, bf[tn][0], bf[tn][1]);
            }
        }
        __syncthreads();
        if (s + 2 < 8) issue(s + 2, s & 1);
    }

    const float scale = 0.17677669529663687f;  // 32^-0.5
#pragma unroll
    for (int tm = 0; tm < 2; tm++)
#pragma unroll
        for (int tn = 0; tn < 8; tn++) {
            int m_g = bm * 64 + wm * 32 + tm * 16 + (lane >> 2);
            int n_g = bn * 128 + wn * 64 + tn * 8 + 2 * (lane & 3);
#pragma unroll
            for (int hf = 0; hf < 2; hf++) {
                int mm = m_g + hf * 8;
                float v0 = acc[tm][tn][hf * 2 + 0] + __ldg(bias + n_g);
                float v1 = acc[tm][tn][hf * 2 + 1] + __ldg(bias + n_g + 1);
                if (epi == 0) {
                    int which = n_g >> 8;
                    int rcol = n_g & 255;
                    int h = rcol >> 5, d = rcol & 31;
                    if (which == 0) { v0 *= scale; v1 *= scale; }
                    int b = mm / NTOK;
                    int t = mm - b * NTOK;
                    size_t idx = ((size_t)which * NWIN * NUM_HEADS + (size_t)b * NUM_HEADS + h)
                                     * (NTOK * HEADDIM)
                                 + t * HEADDIM + d;
                    *(float2*)(g_qkv + idx) = make_float2(v0, v1);
                } else {
                    *(float2*)(out + (size_t)mm * CDIM + n_g) = make_float2(v0, v1);
                }
            }
        }
}

// ---------------------------------------------------------------------------
// Kernel 2: MMA attention per (window, head). 128 threads = 4 warps.
// Tiles padded 50->64. QK via 3xTF32 (hi/lo), PV via tf32 with RNA-consistent P.
// Smem layout (floats), Ps ALIASES qh/ql (dead after QK; barrier-guarded):
//   qh 0..2304, ql 2304..4608, kh 4608..6912, kl 6912..9216,
//   vt 9216..11392 (32x68, transposed V), Ps = 0..4352 (64x68),
//   redmax 11392..11492, redsum 11492..11592, rinv 11592..11656
// ---------------------------------------------------------------------------
__global__ __launch_bounds__(128) void attn_kernel() {
    __shared__ __align__(16) float smem[11656];
    float* qh = smem;
    float* ql = smem + 2304;
    float* kh = smem + 4608;
    float* kl = smem + 6912;
    float* vt = smem + 9216;
    float* Ps = smem;  // aliases qh/ql after QK
    float* redmax = smem + 11392;
    float* redsum = smem + 11492;
    float* rinv = smem + 11592;

    const int bh = blockIdx.x;
    const int b = bh >> 3, h = bh & 7;
    const int tid = threadIdx.x;
    const int lane = tid & 31;
    const int warp = tid >> 5;

    const size_t strideWH = (size_t)NWIN * NUM_HEADS * NTOK * HEADDIM;
    const float* qg = g_qkv + ((size_t)b * NUM_HEADS + h) * (NTOK * HEADDIM);
    const float* kg = qg + strideWH;
    const float* vg = kg + strideWH;

    // zero V pad cols 50..63 (P pad x garbage must not make NaN)
    for (int i = tid; i < 32 * 14; i += 128) {
        int d = i / 14, c = 50 + (i % 14);
        vt[d * 68 + c] = 0.f;
    }
    // load Q,K (hi/lo split) and V (transposed, tf32)
    for (int i = tid; i < 400; i += 128) {
        int r = i >> 3, c4 = (i & 7) * 4;
        float4 q = *(const float4*)(qg + i * 4);
        float4 k = *(const float4*)(kg + i * 4);
        float4 v = *(const float4*)(vg + i * 4);
        float4 qhi = make_float4(tfr(q.x), tfr(q.y), tfr(q.z), tfr(q.w));
        float4 khi = make_float4(tfr(k.x), tfr(k.y), tfr(k.z), tfr(k.w));
        *(float4*)&qh[r * 36 + c4] = qhi;
        *(float4*)&kh[r * 36 + c4] = khi;
        *(float4*)&ql[r * 36 + c4] =
            make_float4(tfr(q.x - qhi.x), tfr(q.y - qhi.y), tfr(q.z - qhi.z), tfr(q.w - qhi.w));
        *(float4*)&kl[r * 36 + c4] =
            make_float4(tfr(k.x - khi.x), tfr(k.y - khi.y), tfr(k.z - khi.z), tfr(k.w - khi.w));
        vt[(c4 + 0) * 68 + r] = tfr(v.x);
        vt[(c4 + 1) * 68 + r] = tfr(v.y);
        vt[(c4 + 2) * 68 + r] = tfr(v.z);
        vt[(c4 + 3) * 68 + r] = tfr(v.w);
    }
    __syncthreads();

    // ---- QK: S[64x64] = Q K^T, 3xTF32. warp w owns rows 16w..16w+15 ----
    float sacc[8][4];
#pragma unroll
    for (int j = 0; j < 8; j++)
#pragma unroll
        for (int r = 0; r < 4; r++) sacc[j][r] = 0.f;

    const int fr = warp * 16 + (lane >> 2);  // A-frag row
#pragma unroll
    for (int ks = 0; ks < 4; ks++) {
        const int kk = ks * 8 + (lane & 3);
        float ah0 = qh[fr * 36 + kk], ah1 = qh[(fr + 8) * 36 + kk];
        float ah2 = qh[fr * 36 + kk + 4], ah3 = qh[(fr + 8) * 36 + kk + 4];
        float al0 = ql[fr * 36 + kk], al1 = ql[(fr + 8) * 36 + kk];
        float al2 = ql[fr * 36 + kk + 4], al3 = ql[(fr + 8) * 36 + kk + 4];
#pragma unroll
        for (int tn = 0; tn < 8; tn++) {
            int n = tn * 8 + (lane >> 2);
            float bh0 = kh[n * 36 + kk], bh1 = kh[n * 36 + kk + 4];
            float bl0 = kl[n * 36 + kk], bl1 = kl[n * 36 + kk + 4];
            mma_tf32f(sacc[tn], ah0, ah1, ah2, ah3, bh0, bh1);
            mma_tf32f(sacc[tn], ah0, ah1, ah2, ah3, bl0, bl1);
            mma_tf32f(sacc[tn], al0, al1, al2, al3, bh0, bh1);
        }
    }
    __syncthreads();  // qh/ql dead only after ALL warps read — Ps aliases them

    // store S to Ps[64x68]
#pragma unroll
    for (int tn = 0; tn < 8; tn++) {
        int c = tn * 8 + 2 * (lane & 3);
        *(float2*)&Ps[fr * 68 + c] = make_float2(sacc[tn][0], sacc[tn][1]);
        *(float2*)&Ps[(fr + 8) * 68 + c] = make_float2(sacc[tn][2], sacc[tn][3]);
    }
    __syncthreads();

    // ---- softmax: row r handled by 2 threads (25 cols each), bias added here ----
    const int r = tid >> 1;
    const int half = tid & 1;
    const float* bg = g_bias + h * (NTOK * NTOK);
    float sv[25];
    if (r < 50) {
        const int cbase = half * 25;
        float smax = -1e30f;
#pragma unroll
        for (int c = 0; c < 25; c++) {
            float a = Ps[r * 68 + cbase + c] + __ldg(bg + r * 50 + cbase + c);
            sv[c] = a;
            smax = fmaxf(smax, a);
        }
        redmax[r * 2 + half] = smax;
    }
    __syncthreads();
    if (r < 50) {
        float m = fmaxf(redmax[r * 2], redmax[r * 2 + 1]);
        const int cbase = half * 25;
        float s = 0.f;
#pragma unroll
        for (int c = 0; c < 25; c++) {
            float e = tfr(__expf(sv[c] - m));  // RNA now -> MMA truncation exact
            Ps[r * 68 + cbase + c] = e;
            s += e;
        }
        redsum[r * 2 + half] = s;
        // zero P pad cols 50..63 (7 per half)
#pragma unroll
        for (int c = 0; c < 7; c++) Ps[r * 68 + 50 + half * 7 + c] = 0.f;
    }
    __syncthreads();
    if (tid < 50) rinv[tid] = 1.f / (redsum[tid * 2] + redsum[tid * 2 + 1]);
    __syncthreads();

    // ---- PV: O[64x32] = P[64x64] V[64x32]; B = vt (V^T), 8 k-steps ----
    float oacc[4][4];
#pragma unroll
    for (int j = 0; j < 4; j++)
#pragma unroll
        for (int t = 0; t < 4; t++) oacc[j][t] = 0.f;
#pragma unroll
    for (int ks = 0; ks < 8; ks++) {
        const int kk = ks * 8 + (lane & 3);
        float a0 = Ps[fr * 68 + kk], a1 = Ps[(fr + 8) * 68 + kk];
        float a2 = Ps[fr * 68 + kk + 4], a3 = Ps[(fr + 8) * 68 + kk + 4];
#pragma unroll
        for (int tn = 0; tn < 4; tn++) {
            int n = tn * 8 + (lane >> 2);
            float b0 = vt[n * 68 + kk], b1 = vt[n * 68 + kk + 4];
            mma_tf32f(oacc[tn], a0, a1, a2, a3, b0, b1);
        }
    }

    // ---- output: normalize, tf32-round, write SW128 image (head = slab) ----
#pragma unroll
    for (int tn = 0; tn < 4; tn++) {
#pragma unroll
        for (int hf = 0; hf < 2; hf++) {
            int row = fr + hf * 8;
            if (row < 50) {
                float rv = rinv[row];
                float v0 = oacc[tn][hf * 2 + 0] * rv;
                float v1 = oacc[tn][hf * 2 + 1] * rv;
                int m = b * NTOK + row;
                int d = tn * 8 + 2 * (lane & 3);
                uint32_t boff = ((uint32_t)(d * 4)) ^ (((uint32_t)m & 7u) << 4);
                float* dst = g_atts + ((size_t)(m >> 6) * 8 + h) * 2048 +
                             (size_t)(m & 63) * 32 + (boff >> 2);
                *(float2*)dst = make_float2(tfr(v0), tfr(v1));
            }
        }
    }
}

// ---------------------------------------------------------------------------
extern "C" void kernel_launch(void* const* d_in, const int* in_sizes, int n_in,
                              void* d_out, int out_size) {
    const float* x = (const float*)d_in[0];
    const float* qkv_w = (const float*)d_in[1];
    const float* qkv_b = (const float*)d_in[2];
    const float* proj_w = (const float*)d_in[3];
    const float* proj_b = (const float*)d_in[4];
    const float* bias_table = (const float*)d_in[5];
    const int* rel_idx = (const int*)d_in[6];
    float* out = (float*)d_out;

    (void)in_sizes; (void)n_in; (void)out_size;

    bias_expand_kernel<<<(NUM_HEADS * NTOK * NTOK + 255) / 256, 256>>>(bias_table, rel_idx);
    wconv_kernel<<<(768 * 64 + 255) / 256, 256>>>(qkv_w, 0, 768);
    wconv_kernel<<<(256 * 64 + 255) / 256, 256>>>(proj_w, 1, 256);
    xconv_kernel<<<(int)(((size_t)MTOT * 64 + 255) / 256), 256>>>(x);
    gemm_cp_kernel<<<dim3(6, 1600), 128>>>(qkv_b, nullptr, 0);
    attn_kernel<<<NWIN * NUM_HEADS, 128>>>();
    gemm_cp_kernel<<<dim3(2, 1600), 128>>>(proj_b, out, 1);
}